// round 3
// baseline (speedup 1.0000x reference)
#include <cuda_runtime.h>
#include <cuda_bf16.h>
#include <cstdint>

#define N_NODES 50000
#define N_EDGES 600000
#define D 128

// Scratch (allocation-free rule: __device__ globals)
__device__ float g_agg1[(size_t)N_NODES * D];
__device__ float g_agg2[(size_t)N_NODES * D];
__device__ float g_h[(size_t)N_NODES * D];
__device__ float g_cnt[N_NODES];

// ---------------------------------------------------------------------------
// Zero scratch (graph replays re-run everything; must re-zero each call)
// ---------------------------------------------------------------------------
__global__ void zero_kernel() {
    const int n4 = (N_NODES * D) / 4;       // 1,600,000 float4 per agg buffer
    const int c4 = N_NODES / 4;             // 12,500 float4 for cnt
    float4 z = make_float4(0.f, 0.f, 0.f, 0.f);
    for (int i = blockIdx.x * blockDim.x + threadIdx.x; i < n4;
         i += gridDim.x * blockDim.x) {
        reinterpret_cast<float4*>(g_agg1)[i] = z;
        reinterpret_cast<float4*>(g_agg2)[i] = z;
        if (i < c4) reinterpret_cast<float4*>(g_cnt)[i] = z;
    }
}

// ---------------------------------------------------------------------------
// Scatter: warp per edge. Gather 512B row of source features (float4/lane),
// scatter-add into agg[dst] with scalar REDG (atomicAdd, result unused).
// Layer 1 also accumulates in-degree counts.
// NOTE: edge_index is int32 (JAX default x64-disabled downgrades int64).
// ---------------------------------------------------------------------------
template <int LAYER>
__global__ void scatter_kernel(const float* __restrict__ x_in,
                               const int* __restrict__ eidx) {
    int warp = (blockIdx.x * blockDim.x + threadIdx.x) >> 5;
    int lane = threadIdx.x & 31;
    if (warp >= N_EDGES) return;

    const float* feat = (LAYER == 1) ? x_in : g_h;
    float* agg = (LAYER == 1) ? g_agg1 : g_agg2;

    int s = __ldg(&eidx[warp]);
    int d = __ldg(&eidx[N_EDGES + warp]);

    float4 v = __ldg(reinterpret_cast<const float4*>(feat + (size_t)s * D) + lane);
    float* p = agg + (size_t)d * D + lane * 4;
    atomicAdd(p + 0, v.x);
    atomicAdd(p + 1, v.y);
    atomicAdd(p + 2, v.z);
    atomicAdd(p + 3, v.w);

    if (LAYER == 1 && lane == 0) atomicAdd(&g_cnt[d], 1.0f);
}

// ---------------------------------------------------------------------------
// Fused SAGE GEMM:  out = (agg/max(cnt,1)) @ W_l + x @ W_r + b   (+relu L1)
// Block = 256 threads handles 64 rows. Both 128x128 W's staged in SMEM.
// Thread tile: 4 rows x 8 cols -> 32 accumulators.
// SMEM: Wl 64KB + Wr 64KB + A 33KB + X 33KB = 194KB (needs opt-in).
// ---------------------------------------------------------------------------
#define MB 64
#define AS 132      // padded row stride (floats) to kill 2-way LDS conflicts
#define GEMM_SMEM_FLOATS (2 * D * D + 2 * MB * AS)
#define GEMM_SMEM_BYTES  (GEMM_SMEM_FLOATS * 4)

__device__ __forceinline__ void gemm_pass(const float* __restrict__ sIn,
                                          const float* __restrict__ sW,
                                          int ry, int cx, float acc[4][8]) {
    const float* a0p = sIn + (ry * 4 + 0) * AS;
    const float* a1p = sIn + (ry * 4 + 1) * AS;
    const float* a2p = sIn + (ry * 4 + 2) * AS;
    const float* a3p = sIn + (ry * 4 + 3) * AS;
#pragma unroll 4
    for (int k = 0; k < D; k++) {
        float a0 = a0p[k], a1 = a1p[k], a2 = a2p[k], a3 = a3p[k];
        const float4* wr = reinterpret_cast<const float4*>(sW + k * D);
        float4 w0 = wr[cx * 2];
        float4 w1 = wr[cx * 2 + 1];
        float w[8] = {w0.x, w0.y, w0.z, w0.w, w1.x, w1.y, w1.z, w1.w};
        float a[4] = {a0, a1, a2, a3};
#pragma unroll
        for (int i = 0; i < 4; i++)
#pragma unroll
            for (int j = 0; j < 8; j++)
                acc[i][j] = fmaf(a[i], w[j], acc[i][j]);
    }
}

template <int LAYER>
__global__ void __launch_bounds__(256, 1)
sage_gemm(const float* __restrict__ x_in,
          const float* __restrict__ Wl, const float* __restrict__ Wr,
          const float* __restrict__ bias, float* __restrict__ d_out) {
    extern __shared__ float sm[];
    float* sWl = sm;                       // D*D
    float* sWr = sm + D * D;               // D*D
    float* sA  = sm + 2 * D * D;           // MB*AS
    float* sX  = sA + MB * AS;             // MB*AS

    const float* agg  = (LAYER == 1) ? g_agg1 : g_agg2;
    const float* feat = (LAYER == 1) ? x_in : g_h;
    float* out        = (LAYER == 1) ? g_h : d_out;

    int tid = threadIdx.x;

    // Stage weights (coalesced float4)
    for (int i = tid; i < (D * D) / 4; i += 256) {
        reinterpret_cast<float4*>(sWl)[i] =
            __ldg(reinterpret_cast<const float4*>(Wl) + i);
        reinterpret_cast<float4*>(sWr)[i] =
            __ldg(reinterpret_cast<const float4*>(Wr) + i);
    }

    // Stage input rows: A = agg * (1/max(cnt,1)), X = feat
    int base = blockIdx.x * MB;
    for (int e = tid; e < MB * (D / 4); e += 256) {
        int r = e >> 5;            // row within block (32 float4 per row)
        int c4 = e & 31;
        int g = base + r;
        float4 va = make_float4(0.f, 0.f, 0.f, 0.f);
        float4 vx = va;
        if (g < N_NODES) {
            float inv = 1.0f / fmaxf(__ldg(&g_cnt[g]), 1.0f);
            va = __ldg(reinterpret_cast<const float4*>(agg + (size_t)g * D) + c4);
            va.x *= inv; va.y *= inv; va.z *= inv; va.w *= inv;
            vx = __ldg(reinterpret_cast<const float4*>(feat + (size_t)g * D) + c4);
        }
        reinterpret_cast<float4*>(sA)[r * (AS / 4) + c4] = va;
        reinterpret_cast<float4*>(sX)[r * (AS / 4) + c4] = vx;
    }
    __syncthreads();

    int cx = tid & 15;     // column group: cols cx*8 .. cx*8+7
    int ry = tid >> 4;     // row group:    rows ry*4 .. ry*4+3

    float acc[4][8];
#pragma unroll
    for (int i = 0; i < 4; i++)
#pragma unroll
        for (int j = 0; j < 8; j++) acc[i][j] = 0.f;

    gemm_pass(sA, sWl, ry, cx, acc);
    gemm_pass(sX, sWr, ry, cx, acc);

    float4 b0 = __ldg(reinterpret_cast<const float4*>(bias) + cx * 2);
    float4 b1 = __ldg(reinterpret_cast<const float4*>(bias) + cx * 2 + 1);
    float bb[8] = {b0.x, b0.y, b0.z, b0.w, b1.x, b1.y, b1.z, b1.w};

#pragma unroll
    for (int i = 0; i < 4; i++) {
        int g = base + ry * 4 + i;
        if (g >= N_NODES) continue;
        float o[8];
#pragma unroll
        for (int j = 0; j < 8; j++) {
            o[j] = acc[i][j] + bb[j];
            if (LAYER == 1) o[j] = fmaxf(o[j], 0.f);
        }
        float4* orow = reinterpret_cast<float4*>(out + (size_t)g * D);
        orow[cx * 2]     = make_float4(o[0], o[1], o[2], o[3]);
        orow[cx * 2 + 1] = make_float4(o[4], o[5], o[6], o[7]);
    }
}

// ---------------------------------------------------------------------------
extern "C" void kernel_launch(void* const* d_in, const int* in_sizes, int n_in,
                              void* d_out, int out_size) {
    const float* x       = (const float*)d_in[0];
    const int* ei        = (const int*)d_in[1];   // int32! (JAX x64 disabled)
    const float* Wl1     = (const float*)d_in[2];
    const float* Wr1     = (const float*)d_in[3];
    const float* b1      = (const float*)d_in[4];
    const float* Wl2     = (const float*)d_in[5];
    const float* Wr2     = (const float*)d_in[6];
    const float* b2      = (const float*)d_in[7];
    float* out           = (float*)d_out;

    cudaFuncSetAttribute(sage_gemm<1>,
                         cudaFuncAttributeMaxDynamicSharedMemorySize,
                         GEMM_SMEM_BYTES);
    cudaFuncSetAttribute(sage_gemm<2>,
                         cudaFuncAttributeMaxDynamicSharedMemorySize,
                         GEMM_SMEM_BYTES);

    // 1. zero scratch
    zero_kernel<<<1184, 256>>>();   // grid-stride over 1.6M float4

    // 2. layer-1 aggregation (+degree counts)
    int scat_blocks = (N_EDGES * 32 + 255) / 256;
    scatter_kernel<1><<<scat_blocks, 256>>>(x, ei);

    // 3. layer-1 fused GEMM + relu -> g_h
    int gemm_blocks = (N_NODES + MB - 1) / MB;
    sage_gemm<1><<<gemm_blocks, 256, GEMM_SMEM_BYTES>>>(x, Wl1, Wr1, b1, out);

    // 4. layer-2 aggregation of h
    scatter_kernel<2><<<scat_blocks, 256>>>(x, ei);

    // 5. layer-2 fused GEMM -> d_out
    sage_gemm<2><<<gemm_blocks, 256, GEMM_SMEM_BYTES>>>(x, Wl2, Wr2, b2, out);
}

// round 4
// speedup vs baseline: 1.7894x; 1.7894x over previous
#include <cuda_runtime.h>
#include <cuda_bf16.h>
#include <cstdint>

#define N_NODES 50000
#define N_EDGES 600000
#define D 128
#define SCAN_B 1024
#define NB ((N_NODES + SCAN_B - 1) / SCAN_B)   // 49 scan blocks

// ---------------------------------------------------------------------------
// Scratch (allocation-free rule: __device__ globals)
// ---------------------------------------------------------------------------
__device__ float g_mean[(size_t)N_NODES * D];  // gather output (reused L1/L2)
__device__ float g_h[(size_t)N_NODES * D];     // layer-1 activations
__device__ int   g_deg[N_NODES];
__device__ int   g_fill[N_NODES];
__device__ int   g_rowptr[N_NODES + 1];
__device__ int   g_bsum[NB];
__device__ int   g_esrc[N_EDGES];

// ---------------------------------------------------------------------------
// CSR build (re-run every call; graph replay repeats all launches)
// ---------------------------------------------------------------------------
__global__ void zero_csr() {
    int i = blockIdx.x * blockDim.x + threadIdx.x;
    if (i < N_NODES) { g_deg[i] = 0; g_fill[i] = 0; }
}

__global__ void hist_kernel(const int* __restrict__ eidx) {
    int e = blockIdx.x * blockDim.x + threadIdx.x;
    if (e < N_EDGES) atomicAdd(&g_deg[__ldg(&eidx[N_EDGES + e])], 1);
}

__global__ void scan_block() {
    __shared__ int sm[SCAN_B];
    int tid = threadIdx.x;
    int gid = blockIdx.x * SCAN_B + tid;
    int v = (gid < N_NODES) ? g_deg[gid] : 0;
    sm[tid] = v;
    __syncthreads();
#pragma unroll
    for (int off = 1; off < SCAN_B; off <<= 1) {
        int t = (tid >= off) ? sm[tid - off] : 0;
        __syncthreads();
        sm[tid] += t;
        __syncthreads();
    }
    if (gid < N_NODES) g_rowptr[gid + 1] = sm[tid];
    if (tid == SCAN_B - 1) g_bsum[blockIdx.x] = sm[tid];
}

__global__ void scan_partials() {
    if (threadIdx.x == 0) {
        int acc = 0;
        for (int i = 0; i < NB; i++) { int t = g_bsum[i]; g_bsum[i] = acc; acc += t; }
    }
}

__global__ void scan_add() {
    int tid = threadIdx.x;
    int gid = blockIdx.x * SCAN_B + tid;
    if (gid < N_NODES) g_rowptr[gid + 1] += g_bsum[blockIdx.x];
    if (gid == 0) g_rowptr[0] = 0;
}

__global__ void fill_kernel(const int* __restrict__ eidx) {
    int e = blockIdx.x * blockDim.x + threadIdx.x;
    if (e >= N_EDGES) return;
    int s = __ldg(&eidx[e]);
    int d = __ldg(&eidx[N_EDGES + e]);
    int slot = atomicAdd(&g_fill[d], 1);
    g_esrc[g_rowptr[d] + slot] = s;
}

// ---------------------------------------------------------------------------
// Gather-side mean aggregation: one warp per dst node, register accumulation,
// single coalesced write. No atomics on the feature data at all.
// ---------------------------------------------------------------------------
template <int LAYER>
__global__ void gather_kernel(const float* __restrict__ x_in) {
    int warp = (blockIdx.x * blockDim.x + threadIdx.x) >> 5;
    int lane = threadIdx.x & 31;
    if (warp >= N_NODES) return;

    const float* feat = (LAYER == 1) ? x_in : g_h;

    int beg = __ldg(&g_rowptr[warp]);
    int end = __ldg(&g_rowptr[warp + 1]);

    float4 acc = make_float4(0.f, 0.f, 0.f, 0.f);
    int j = beg;
    // unroll 4 for MLP: 4 independent 512B row reads in flight per warp
    for (; j + 4 <= end; j += 4) {
        int s0 = __ldg(&g_esrc[j + 0]);
        int s1 = __ldg(&g_esrc[j + 1]);
        int s2 = __ldg(&g_esrc[j + 2]);
        int s3 = __ldg(&g_esrc[j + 3]);
        float4 v0 = __ldg(reinterpret_cast<const float4*>(feat + (size_t)s0 * D) + lane);
        float4 v1 = __ldg(reinterpret_cast<const float4*>(feat + (size_t)s1 * D) + lane);
        float4 v2 = __ldg(reinterpret_cast<const float4*>(feat + (size_t)s2 * D) + lane);
        float4 v3 = __ldg(reinterpret_cast<const float4*>(feat + (size_t)s3 * D) + lane);
        acc.x += (v0.x + v1.x) + (v2.x + v3.x);
        acc.y += (v0.y + v1.y) + (v2.y + v3.y);
        acc.z += (v0.z + v1.z) + (v2.z + v3.z);
        acc.w += (v0.w + v1.w) + (v2.w + v3.w);
    }
    for (; j < end; j++) {
        int s = __ldg(&g_esrc[j]);
        float4 v = __ldg(reinterpret_cast<const float4*>(feat + (size_t)s * D) + lane);
        acc.x += v.x; acc.y += v.y; acc.z += v.z; acc.w += v.w;
    }

    float inv = 1.0f / fmaxf((float)(end - beg), 1.0f);
    acc.x *= inv; acc.y *= inv; acc.z *= inv; acc.w *= inv;
    reinterpret_cast<float4*>(g_mean + (size_t)warp * D)[lane] = acc;
}

// ---------------------------------------------------------------------------
// Fused SAGE GEMM:  out = mean @ W_l + x @ W_r + b   (+relu in layer 1)
// Block = 256 threads handles 64 rows. Both 128x128 W's staged in SMEM.
// Thread tile: 4 rows x 8 cols. a-operand LDS vectorized over k (float4).
// SMEM: Wl 64KB + Wr 64KB + A 33KB + X 33KB = 194KB (opt-in).
// ---------------------------------------------------------------------------
#define MB 64
#define AS 132      // padded row stride (floats); divisible by 4 for float4
#define GEMM_SMEM_FLOATS (2 * D * D + 2 * MB * AS)
#define GEMM_SMEM_BYTES  (GEMM_SMEM_FLOATS * 4)

__device__ __forceinline__ void gemm_pass(const float* __restrict__ sIn,
                                          const float* __restrict__ sW,
                                          int ry, int cx, float acc[4][8]) {
    const float4* a0p = reinterpret_cast<const float4*>(sIn + (ry * 4 + 0) * AS);
    const float4* a1p = reinterpret_cast<const float4*>(sIn + (ry * 4 + 1) * AS);
    const float4* a2p = reinterpret_cast<const float4*>(sIn + (ry * 4 + 2) * AS);
    const float4* a3p = reinterpret_cast<const float4*>(sIn + (ry * 4 + 3) * AS);
#pragma unroll 2
    for (int k4 = 0; k4 < D / 4; k4++) {
        float4 av[4] = {a0p[k4], a1p[k4], a2p[k4], a3p[k4]};
#pragma unroll
        for (int kk = 0; kk < 4; kk++) {
            int k = k4 * 4 + kk;
            const float4* wr = reinterpret_cast<const float4*>(sW + k * D);
            float4 w0 = wr[cx * 2];
            float4 w1 = wr[cx * 2 + 1];
            float w[8] = {w0.x, w0.y, w0.z, w0.w, w1.x, w1.y, w1.z, w1.w};
#pragma unroll
            for (int i = 0; i < 4; i++) {
                float a = reinterpret_cast<const float*>(&av[i])[kk];
#pragma unroll
                for (int jx = 0; jx < 8; jx++)
                    acc[i][jx] = fmaf(a, w[jx], acc[i][jx]);
            }
        }
    }
}

template <int LAYER>
__global__ void __launch_bounds__(256, 1)
sage_gemm(const float* __restrict__ x_in,
          const float* __restrict__ Wl, const float* __restrict__ Wr,
          const float* __restrict__ bias, float* __restrict__ d_out) {
    extern __shared__ float sm[];
    float* sWl = sm;                       // D*D
    float* sWr = sm + D * D;               // D*D
    float* sA  = sm + 2 * D * D;           // MB*AS
    float* sX  = sA + MB * AS;             // MB*AS

    const float* feat = (LAYER == 1) ? x_in : g_h;
    float* out        = (LAYER == 1) ? g_h : d_out;

    int tid = threadIdx.x;

    // Stage weights (coalesced float4)
    for (int i = tid; i < (D * D) / 4; i += 256) {
        reinterpret_cast<float4*>(sWl)[i] =
            __ldg(reinterpret_cast<const float4*>(Wl) + i);
        reinterpret_cast<float4*>(sWr)[i] =
            __ldg(reinterpret_cast<const float4*>(Wr) + i);
    }

    // Stage input rows: A = mean (already divided), X = feat
    int base = blockIdx.x * MB;
    for (int e = tid; e < MB * (D / 4); e += 256) {
        int r = e >> 5;            // row within block (32 float4 per row)
        int c4 = e & 31;
        int g = base + r;
        float4 va = make_float4(0.f, 0.f, 0.f, 0.f);
        float4 vx = va;
        if (g < N_NODES) {
            va = __ldg(reinterpret_cast<const float4*>(g_mean + (size_t)g * D) + c4);
            vx = __ldg(reinterpret_cast<const float4*>(feat + (size_t)g * D) + c4);
        }
        reinterpret_cast<float4*>(sA)[r * (AS / 4) + c4] = va;
        reinterpret_cast<float4*>(sX)[r * (AS / 4) + c4] = vx;
    }
    __syncthreads();

    int cx = tid & 15;     // column group: cols cx*8 .. cx*8+7
    int ry = tid >> 4;     // row group:    rows ry*4 .. ry*4+3

    float acc[4][8];
#pragma unroll
    for (int i = 0; i < 4; i++)
#pragma unroll
        for (int j = 0; j < 8; j++) acc[i][j] = 0.f;

    gemm_pass(sA, sWl, ry, cx, acc);
    gemm_pass(sX, sWr, ry, cx, acc);

    float4 b0 = __ldg(reinterpret_cast<const float4*>(bias) + cx * 2);
    float4 b1 = __ldg(reinterpret_cast<const float4*>(bias) + cx * 2 + 1);
    float bb[8] = {b0.x, b0.y, b0.z, b0.w, b1.x, b1.y, b1.z, b1.w};

#pragma unroll
    for (int i = 0; i < 4; i++) {
        int g = base + ry * 4 + i;
        if (g >= N_NODES) continue;
        float o[8];
#pragma unroll
        for (int j = 0; j < 8; j++) {
            o[j] = acc[i][j] + bb[j];
            if (LAYER == 1) o[j] = fmaxf(o[j], 0.f);
        }
        float4* orow = reinterpret_cast<float4*>(out + (size_t)g * D);
        orow[cx * 2]     = make_float4(o[0], o[1], o[2], o[3]);
        orow[cx * 2 + 1] = make_float4(o[4], o[5], o[6], o[7]);
    }
}

// ---------------------------------------------------------------------------
extern "C" void kernel_launch(void* const* d_in, const int* in_sizes, int n_in,
                              void* d_out, int out_size) {
    const float* x       = (const float*)d_in[0];
    const int* ei        = (const int*)d_in[1];   // int32 (JAX x64 disabled)
    const float* Wl1     = (const float*)d_in[2];
    const float* Wr1     = (const float*)d_in[3];
    const float* b1      = (const float*)d_in[4];
    const float* Wl2     = (const float*)d_in[5];
    const float* Wr2     = (const float*)d_in[6];
    const float* b2      = (const float*)d_in[7];
    float* out           = (float*)d_out;

    cudaFuncSetAttribute(sage_gemm<1>,
                         cudaFuncAttributeMaxDynamicSharedMemorySize,
                         GEMM_SMEM_BYTES);
    cudaFuncSetAttribute(sage_gemm<2>,
                         cudaFuncAttributeMaxDynamicSharedMemorySize,
                         GEMM_SMEM_BYTES);

    int eb = (N_EDGES + 255) / 256;

    // CSR build (per call; deterministic up to bucket order)
    zero_csr<<<(N_NODES + 255) / 256, 256>>>();
    hist_kernel<<<eb, 256>>>(ei);
    scan_block<<<NB, SCAN_B>>>();
    scan_partials<<<1, 32>>>();
    scan_add<<<NB, SCAN_B>>>();
    fill_kernel<<<eb, 256>>>(ei);

    int gather_blocks = (N_NODES * 32 + 255) / 256;
    int gemm_blocks = (N_NODES + MB - 1) / MB;

    // Layer 1
    gather_kernel<1><<<gather_blocks, 256>>>(x);
    sage_gemm<1><<<gemm_blocks, 256, GEMM_SMEM_BYTES>>>(x, Wl1, Wr1, b1, out);

    // Layer 2
    gather_kernel<2><<<gather_blocks, 256>>>(x);
    sage_gemm<2><<<gemm_blocks, 256, GEMM_SMEM_BYTES>>>(x, Wl2, Wr2, b2, out);
}

// round 6
// speedup vs baseline: 4.0911x; 2.2863x over previous
#include <cuda_runtime.h>
#include <cuda_bf16.h>
#include <cstdint>

#define N_NODES 50000
#define N_EDGES 600000
#define D 128
#define SCAN_B 1024
#define NB ((N_NODES + SCAN_B - 1) / SCAN_B)   // 49 scan blocks

// ---------------------------------------------------------------------------
// Scratch (allocation-free rule: __device__ globals)
// ---------------------------------------------------------------------------
__device__ float g_mean[(size_t)N_NODES * D];  // gather output
__device__ float g_h[(size_t)N_NODES * D];     // layer-1 activations
__device__ int   g_deg[N_NODES];
__device__ int   g_fill[N_NODES];
__device__ int   g_rowptr[N_NODES + 1];
__device__ int   g_bsum[NB];
__device__ int   g_esrc[N_EDGES];

__device__ __forceinline__ float to_tf32(float f) {
    float r;
    asm("cvt.rna.tf32.f32 %0, %1;" : "=f"(r) : "f"(f));
    return r;
}

// ---------------------------------------------------------------------------
// CSR build
// ---------------------------------------------------------------------------
__global__ void zero_csr() {
    int i = blockIdx.x * blockDim.x + threadIdx.x;
    if (i < N_NODES) { g_deg[i] = 0; g_fill[i] = 0; }
}

__global__ void hist_kernel(const int* __restrict__ eidx) {
    int e = blockIdx.x * blockDim.x + threadIdx.x;
    if (e < N_EDGES) atomicAdd(&g_deg[__ldg(&eidx[N_EDGES + e])], 1);
}

__global__ void scan_block() {
    __shared__ int sm[SCAN_B];
    int tid = threadIdx.x;
    int gid = blockIdx.x * SCAN_B + tid;
    int v = (gid < N_NODES) ? g_deg[gid] : 0;
    sm[tid] = v;
    __syncthreads();
#pragma unroll
    for (int off = 1; off < SCAN_B; off <<= 1) {
        int t = (tid >= off) ? sm[tid - off] : 0;
        __syncthreads();
        sm[tid] += t;
        __syncthreads();
    }
    if (gid < N_NODES) g_rowptr[gid + 1] = sm[tid];
    if (tid == SCAN_B - 1) g_bsum[blockIdx.x] = sm[tid];
}

__global__ void scan_partials() {   // warp shfl scan over NB=49 partials
    int lane = threadIdx.x;
    int carry = 0;
    for (int base = 0; base < NB; base += 32) {
        int i = base + lane;
        int v = (i < NB) ? g_bsum[i] : 0;
        int inc = v;
#pragma unroll
        for (int o = 1; o < 32; o <<= 1) {
            int u = __shfl_up_sync(0xffffffffu, inc, o);
            if (lane >= o) inc += u;
        }
        if (i < NB) g_bsum[i] = inc - v + carry;   // exclusive prefix + carry
        carry += __shfl_sync(0xffffffffu, inc, 31);
    }
}

__global__ void scan_add() {
    int tid = threadIdx.x;
    int gid = blockIdx.x * SCAN_B + tid;
    if (gid < N_NODES) g_rowptr[gid + 1] += g_bsum[blockIdx.x];
    if (gid == 0) g_rowptr[0] = 0;
}

__global__ void fill_kernel(const int* __restrict__ eidx) {
    int e = blockIdx.x * blockDim.x + threadIdx.x;
    if (e >= N_EDGES) return;
    int s = __ldg(&eidx[e]);
    int d = __ldg(&eidx[N_EDGES + e]);
    int slot = atomicAdd(&g_fill[d], 1);
    g_esrc[g_rowptr[d] + slot] = s;
}

// ---------------------------------------------------------------------------
// Gather-side mean aggregation (one warp per dst node, register accumulation)
// ---------------------------------------------------------------------------
template <int LAYER>
__global__ void gather_kernel(const float* __restrict__ x_in) {
    int warp = (blockIdx.x * blockDim.x + threadIdx.x) >> 5;
    int lane = threadIdx.x & 31;
    if (warp >= N_NODES) return;

    const float* feat = (LAYER == 1) ? x_in : g_h;

    int beg = __ldg(&g_rowptr[warp]);
    int end = __ldg(&g_rowptr[warp + 1]);

    float4 acc = make_float4(0.f, 0.f, 0.f, 0.f);
    int j = beg;
    for (; j + 4 <= end; j += 4) {
        int s0 = __ldg(&g_esrc[j + 0]);
        int s1 = __ldg(&g_esrc[j + 1]);
        int s2 = __ldg(&g_esrc[j + 2]);
        int s3 = __ldg(&g_esrc[j + 3]);
        float4 v0 = __ldg(reinterpret_cast<const float4*>(feat + (size_t)s0 * D) + lane);
        float4 v1 = __ldg(reinterpret_cast<const float4*>(feat + (size_t)s1 * D) + lane);
        float4 v2 = __ldg(reinterpret_cast<const float4*>(feat + (size_t)s2 * D) + lane);
        float4 v3 = __ldg(reinterpret_cast<const float4*>(feat + (size_t)s3 * D) + lane);
        acc.x += (v0.x + v1.x) + (v2.x + v3.x);
        acc.y += (v0.y + v1.y) + (v2.y + v3.y);
        acc.z += (v0.z + v1.z) + (v2.z + v3.z);
        acc.w += (v0.w + v1.w) + (v2.w + v3.w);
    }
    for (; j < end; j++) {
        int s = __ldg(&g_esrc[j]);
        float4 v = __ldg(reinterpret_cast<const float4*>(feat + (size_t)s * D) + lane);
        acc.x += v.x; acc.y += v.y; acc.z += v.z; acc.w += v.w;
    }

    float inv = 1.0f / fmaxf((float)(end - beg), 1.0f);
    acc.x *= inv; acc.y *= inv; acc.z *= inv; acc.w *= inv;
    reinterpret_cast<float4*>(g_mean + (size_t)warp * D)[lane] = acc;
}

// ---------------------------------------------------------------------------
// tf32 mma.sync GEMM: out = mean @ Wl + feat @ Wr + b (+relu L1)
// CTA = 128 rows x 128 cols, 8 warps, each warp an m16 x n128 strip.
// K=256 via two staged passes, fp32 register accumulators.
// A tile: [128][132] fp32 (tf32-rounded); W tile: [128][136].
// Fragment LDS strides chosen for 0-conflict (see banks derivation).
// ---------------------------------------------------------------------------
#define ASA 132
#define WSB 136
#define TCSM ((128 * ASA + 128 * WSB) * 4)   // 134 KB

__device__ __forceinline__ void mma_tf32(float c[4], uint32_t a0, uint32_t a1,
                                         uint32_t a2, uint32_t a3,
                                         uint32_t b0, uint32_t b1) {
    asm volatile(
        "mma.sync.aligned.m16n8k8.row.col.f32.tf32.tf32.f32 "
        "{%0,%1,%2,%3}, {%4,%5,%6,%7}, {%8,%9}, {%0,%1,%2,%3};"
        : "+f"(c[0]), "+f"(c[1]), "+f"(c[2]), "+f"(c[3])
        : "r"(a0), "r"(a1), "r"(a2), "r"(a3), "r"(b0), "r"(b1));
}

template <int LAYER>
__global__ void __launch_bounds__(256, 1)
sage_gemm_mma(const float* __restrict__ x_in,
              const float* __restrict__ Wl, const float* __restrict__ Wr,
              const float* __restrict__ bias, float* __restrict__ d_out) {
    extern __shared__ float sm[];
    float* sA = sm;                 // [128][ASA]
    float* sW = sm + 128 * ASA;     // [128][WSB]

    int tid = threadIdx.x;
    int wid = tid >> 5;
    int lane = tid & 31;
    int gid = lane >> 2;            // 0..7
    int tig = lane & 3;             // 0..3
    int base = blockIdx.x * 128;

    const float* feat = (LAYER == 1) ? x_in : g_h;
    float* out        = (LAYER == 1) ? g_h : d_out;

    float c[16][4];
#pragma unroll
    for (int nt = 0; nt < 16; nt++)
#pragma unroll
        for (int q = 0; q < 4; q++) c[nt][q] = 0.f;

#pragma unroll
    for (int pass = 0; pass < 2; pass++) {
        const float* Asrc = (pass == 0) ? g_mean : feat;
        const float* Wsrc = (pass == 0) ? Wl : Wr;

        if (pass) __syncthreads();   // all warps done reading pass-0 tiles

        // Stage A: 128 rows x 32 float4, tf32-rounded
        for (int e = tid; e < 128 * 32; e += 256) {
            int r = e >> 5, c4 = e & 31;
            int g = base + r;
            float4 v = make_float4(0.f, 0.f, 0.f, 0.f);
            if (g < N_NODES)
                v = __ldg(reinterpret_cast<const float4*>(Asrc + (size_t)g * D) + c4);
            v.x = to_tf32(v.x); v.y = to_tf32(v.y);
            v.z = to_tf32(v.z); v.w = to_tf32(v.w);
            *reinterpret_cast<float4*>(sA + r * ASA + c4 * 4) = v;
        }
        // Stage W (row-major [k][n], used directly as col-frag B)
        for (int e = tid; e < 128 * 32; e += 256) {
            int r = e >> 5, c4 = e & 31;
            float4 v = __ldg(reinterpret_cast<const float4*>(Wsrc + (size_t)r * D) + c4);
            v.x = to_tf32(v.x); v.y = to_tf32(v.y);
            v.z = to_tf32(v.z); v.w = to_tf32(v.w);
            *reinterpret_cast<float4*>(sW + r * WSB + c4 * 4) = v;
        }
        __syncthreads();

        const float* Awarp = sA + (wid * 16 + gid) * ASA + tig;
#pragma unroll 4
        for (int ks = 0; ks < 16; ks++) {
            const float* ap = Awarp + ks * 8;
            uint32_t a0 = __float_as_uint(ap[0]);
            uint32_t a1 = __float_as_uint(ap[8 * ASA]);
            uint32_t a2 = __float_as_uint(ap[4]);
            uint32_t a3 = __float_as_uint(ap[8 * ASA + 4]);
            const float* bp = sW + (ks * 8 + tig) * WSB + gid;
#pragma unroll
            for (int nt = 0; nt < 16; nt++) {
                uint32_t b0 = __float_as_uint(bp[nt * 8]);
                uint32_t b1 = __float_as_uint(bp[4 * WSB + nt * 8]);
                mma_tf32(c[nt], a0, a1, a2, a3, b0, b1);
            }
        }
    }

    // Epilogue: bias (+relu), direct register->gmem store
    int row0 = base + wid * 16 + gid;
#pragma unroll
    for (int nt = 0; nt < 16; nt++) {
        int col = nt * 8 + 2 * tig;
        float2 bb = *reinterpret_cast<const float2*>(bias + col);
        float o0 = c[nt][0] + bb.x, o1 = c[nt][1] + bb.y;
        float o2 = c[nt][2] + bb.x, o3 = c[nt][3] + bb.y;
        if (LAYER == 1) {
            o0 = fmaxf(o0, 0.f); o1 = fmaxf(o1, 0.f);
            o2 = fmaxf(o2, 0.f); o3 = fmaxf(o3, 0.f);
        }
        if (row0 < N_NODES)
            *reinterpret_cast<float2*>(out + (size_t)row0 * D + col) = make_float2(o0, o1);
        if (row0 + 8 < N_NODES)
            *reinterpret_cast<float2*>(out + (size_t)(row0 + 8) * D + col) = make_float2(o2, o3);
    }
}

// ---------------------------------------------------------------------------
extern "C" void kernel_launch(void* const* d_in, const int* in_sizes, int n_in,
                              void* d_out, int out_size) {
    const float* x       = (const float*)d_in[0];
    const int* ei        = (const int*)d_in[1];   // int32 (JAX x64 disabled)
    const float* Wl1     = (const float*)d_in[2];
    const float* Wr1     = (const float*)d_in[3];
    const float* b1      = (const float*)d_in[4];
    const float* Wl2     = (const float*)d_in[5];
    const float* Wr2     = (const float*)d_in[6];
    const float* b2      = (const float*)d_in[7];
    float* out           = (float*)d_out;

    cudaFuncSetAttribute(sage_gemm_mma<1>,
                         cudaFuncAttributeMaxDynamicSharedMemorySize, TCSM);
    cudaFuncSetAttribute(sage_gemm_mma<2>,
                         cudaFuncAttributeMaxDynamicSharedMemorySize, TCSM);

    int eb = (N_EDGES + 255) / 256;

    // CSR build
    zero_csr<<<(N_NODES + 255) / 256, 256>>>();
    hist_kernel<<<eb, 256>>>(ei);
    scan_block<<<NB, SCAN_B>>>();
    scan_partials<<<1, 32>>>();
    scan_add<<<NB, SCAN_B>>>();
    fill_kernel<<<eb, 256>>>(ei);

    int gather_blocks = (N_NODES * 32 + 255) / 256;
    int gemm_blocks = (N_NODES + 127) / 128;

    // Layer 1
    gather_kernel<1><<<gather_blocks, 256>>>(x);
    sage_gemm_mma<1><<<gemm_blocks, 256, TCSM>>>(x, Wl1, Wr1, b1, out);

    // Layer 2
    gather_kernel<2><<<gather_blocks, 256>>>(x);
    sage_gemm_mma<2><<<gemm_blocks, 256, TCSM>>>(x, Wl2, Wr2, b2, out);
}